// round 8
// baseline (speedup 1.0000x reference)
#include <cuda_runtime.h>
#include <cuda_bf16.h>

#define NMAX 100000
#define MAXDEG 64

// ---------------- scratch (allocation-free) ----------------
__device__ float g_m[(size_t)NMAX * 128];
__device__ float g_h[(size_t)NMAX * 128];
__device__ int g_counts[NMAX];                    // zero-initialized at load
__device__ int g_slots[(size_t)NMAX * MAXDEG];    // incoming src per node
__device__ unsigned short g_wthi[2][128 * 128];
__device__ unsigned short g_wtlo[2][128 * 128];

__device__ __forceinline__ unsigned smem_u32(const void* p) {
    unsigned a;
    asm("{ .reg .u64 t; cvta.to.shared.u64 t, %1; cvt.u32.u64 %0, t; }" : "=r"(a) : "l"(p));
    return a;
}

// Tile layout for a bf16 operand: row-major 256B rows; 16B chunks XOR-swizzled.
__device__ __forceinline__ unsigned tile_off(int row, int k) {
    return (unsigned)(row * 256 + ((((k >> 3) ^ (row & 7))) << 4) + (k & 7) * 2);
}

// ---------------------------------------------------------------------------
// Fused prep: blocks [0,128) convert W^T to bf16 hi/lo tiles;
// blocks [128, ...) place edges into the slot table.
// ---------------------------------------------------------------------------
__global__ void prep_kernel(const float* __restrict__ W1, const float* __restrict__ W2,
                            const int* __restrict__ src, const int* __restrict__ dst,
                            int* __restrict__ counts, int* __restrict__ slots, int E) {
    if (blockIdx.x < 128) {
        int id = blockIdx.x * 256 + threadIdx.x;   // 0..32767
        int layer = id >> 14;
        int nn = (id >> 7) & 127;
        int k = id & 127;
        const float* W = layer ? W2 : W1;
        float v = W[k * 128 + nn];                 // W^T[n][k]
        __nv_bfloat16 h = __float2bfloat16(v);
        __nv_bfloat16 l = __float2bfloat16(v - __bfloat162float(h));
        unsigned idx = tile_off(nn, k) >> 1;
        g_wthi[layer][idx] = *reinterpret_cast<unsigned short*>(&h);
        g_wtlo[layer][idx] = *reinterpret_cast<unsigned short*>(&l);
    } else {
        int e = (blockIdx.x - 128) * 256 + threadIdx.x;
        if (e < E) {
            int d = dst[e];
            int pos = atomicAdd(&counts[d], 1);
            if (pos < MAXDEG) slots[(size_t)d * MAXDEG + pos] = src[e];
        }
    }
}

// ---------------------------------------------------------------------------
// Persistent tensor-core GEMM: C[N,128] = (relu?)(A[N,128]) @ W
// Grid 296 (2 CTA/SM). W hi/lo loaded ONCE per block; stride over 64-row tiles.
// smem: A_hi 16K | A_lo 16K | W_hi 32K | W_lo 32K = 98304 B.
// 3 passes: Ah*Wh + Ah*Wl + Al*Wh, fp32 accum.
// ---------------------------------------------------------------------------
#define AHI 0
#define ALO 16384
#define WHI 32768
#define WLO 65536
#define GEMM_SMEM 98304

__global__ __launch_bounds__(256, 2) void gemm_mma(
    const float* __restrict__ A, const unsigned short* __restrict__ Whi,
    const unsigned short* __restrict__ Wlo, float* __restrict__ C,
    int N, int applyRelu, int numTiles) {
    extern __shared__ __align__(128) char smem[];
    const unsigned sb = smem_u32(smem);
    const int tx = threadIdx.x;
    const int wid = tx >> 5;
    const int lane = tx & 31;

    // Load W hi/lo once (2048 uint4 each).
    {
        const uint4* wh = (const uint4*)Whi;
        const uint4* wl = (const uint4*)Wlo;
        uint4* sh = (uint4*)(smem + WHI);
        uint4* sl = (uint4*)(smem + WLO);
#pragma unroll
        for (int i = 0; i < 8; i++) {
            sh[tx + 256 * i] = wh[tx + 256 * i];
            sl[tx + 256 * i] = wl[tx + 256 * i];
        }
    }

    // Per-lane mma addressing constants.
    const int m0 = (wid >> 2) * 32;
    const int n0 = (wid & 3) * 32;
    const int a_row_l = lane & 15;
    const int a_half = lane >> 4;
    const int b_row_l = ((lane >> 4) << 3) + (lane & 7);
    const int b_half = (lane >> 3) & 1;
    unsigned a_base[2], b_base[2];
#pragma unroll
    for (int i = 0; i < 2; i++) {
        a_base[i] = (unsigned)((m0 + i * 16 + a_row_l) * 256);
        b_base[i] = (unsigned)((n0 + i * 16 + b_row_l) * 256);
    }
    const int sw_a = a_row_l & 7;
    const int sw_b = b_row_l & 7;

    for (int tile = blockIdx.x; tile < numTiles; tile += gridDim.x) {
        const int row0 = tile * 64;
        __syncthreads();   // prior iter's ldmatrix reads done (and W fill on iter 0)

        // Load A tile (64 rows x 16 chunks), split hi/lo, store swizzled.
        {
            const float4* A4 = (const float4*)A;
#pragma unroll
            for (int i = 0; i < 4; i++) {
                int li = tx + 256 * i;
                int r = li >> 4;
                int kc = li & 15;
                int row = row0 + r;
                float4 v0 = make_float4(0.f, 0.f, 0.f, 0.f);
                float4 v1 = v0;
                if (row < N) {
                    v0 = A4[(size_t)row * 32 + kc * 2];
                    v1 = A4[(size_t)row * 32 + kc * 2 + 1];
                    if (applyRelu) {
                        v0.x = fmaxf(v0.x, 0.f); v0.y = fmaxf(v0.y, 0.f);
                        v0.z = fmaxf(v0.z, 0.f); v0.w = fmaxf(v0.w, 0.f);
                        v1.x = fmaxf(v1.x, 0.f); v1.y = fmaxf(v1.y, 0.f);
                        v1.z = fmaxf(v1.z, 0.f); v1.w = fmaxf(v1.w, 0.f);
                    }
                }
                __nv_bfloat162 h0 = __floats2bfloat162_rn(v0.x, v0.y);
                __nv_bfloat162 h1 = __floats2bfloat162_rn(v0.z, v0.w);
                __nv_bfloat162 h2 = __floats2bfloat162_rn(v1.x, v1.y);
                __nv_bfloat162 h3 = __floats2bfloat162_rn(v1.z, v1.w);
                float2 f0 = __bfloat1622float2(h0);
                float2 f1 = __bfloat1622float2(h1);
                float2 f2 = __bfloat1622float2(h2);
                float2 f3 = __bfloat1622float2(h3);
                __nv_bfloat162 l0 = __floats2bfloat162_rn(v0.x - f0.x, v0.y - f0.y);
                __nv_bfloat162 l1 = __floats2bfloat162_rn(v0.z - f1.x, v0.w - f1.y);
                __nv_bfloat162 l2 = __floats2bfloat162_rn(v1.x - f2.x, v1.y - f2.y);
                __nv_bfloat162 l3 = __floats2bfloat162_rn(v1.z - f3.x, v1.w - f3.y);
                unsigned off = (unsigned)(r * 256 + ((kc ^ (r & 7)) << 4));
                *(uint4*)(smem + AHI + off) = make_uint4(
                    *reinterpret_cast<unsigned*>(&h0), *reinterpret_cast<unsigned*>(&h1),
                    *reinterpret_cast<unsigned*>(&h2), *reinterpret_cast<unsigned*>(&h3));
                *(uint4*)(smem + ALO + off) = make_uint4(
                    *reinterpret_cast<unsigned*>(&l0), *reinterpret_cast<unsigned*>(&l1),
                    *reinterpret_cast<unsigned*>(&l2), *reinterpret_cast<unsigned*>(&l3));
            }
        }
        __syncthreads();

        float c[2][4][4];
#pragma unroll
        for (int mi = 0; mi < 2; mi++)
#pragma unroll
            for (int nj = 0; nj < 4; nj++)
#pragma unroll
                for (int q = 0; q < 4; q++) c[mi][nj][q] = 0.f;

#pragma unroll
        for (int p = 0; p < 3; p++) {
            const unsigned Ab = sb + (p == 2 ? ALO : AHI);
            const unsigned Wb = sb + (p == 1 ? WLO : WHI);
#pragma unroll
            for (int kk = 0; kk < 8; kk++) {
                const int kc = kk * 2;
                unsigned a0[2], a1[2], a2[2], a3[2];
#pragma unroll
                for (int mi = 0; mi < 2; mi++) {
                    unsigned addr = Ab + a_base[mi] + ((((kc + a_half) ^ sw_a)) << 4);
                    asm volatile("ldmatrix.sync.aligned.m8n8.x4.shared.b16 {%0,%1,%2,%3}, [%4];"
                                 : "=r"(a0[mi]), "=r"(a1[mi]), "=r"(a2[mi]), "=r"(a3[mi])
                                 : "r"(addr));
                }
#pragma unroll
                for (int nj = 0; nj < 2; nj++) {
                    unsigned b0, b1, b2, b3;
                    unsigned addr = Wb + b_base[nj] + ((((kc + b_half) ^ sw_b)) << 4);
                    asm volatile("ldmatrix.sync.aligned.m8n8.x4.shared.b16 {%0,%1,%2,%3}, [%4];"
                                 : "=r"(b0), "=r"(b1), "=r"(b2), "=r"(b3)
                                 : "r"(addr));
#pragma unroll
                    for (int mi = 0; mi < 2; mi++) {
                        asm volatile(
                            "mma.sync.aligned.m16n8k16.row.col.f32.bf16.bf16.f32 "
                            "{%0,%1,%2,%3}, {%4,%5,%6,%7}, {%8,%9}, {%0,%1,%2,%3};"
                            : "+f"(c[mi][nj * 2][0]), "+f"(c[mi][nj * 2][1]),
                              "+f"(c[mi][nj * 2][2]), "+f"(c[mi][nj * 2][3])
                            : "r"(a0[mi]), "r"(a1[mi]), "r"(a2[mi]), "r"(a3[mi]),
                              "r"(b0), "r"(b1));
                        asm volatile(
                            "mma.sync.aligned.m16n8k16.row.col.f32.bf16.bf16.f32 "
                            "{%0,%1,%2,%3}, {%4,%5,%6,%7}, {%8,%9}, {%0,%1,%2,%3};"
                            : "+f"(c[mi][nj * 2 + 1][0]), "+f"(c[mi][nj * 2 + 1][1]),
                              "+f"(c[mi][nj * 2 + 1][2]), "+f"(c[mi][nj * 2 + 1][3])
                            : "r"(a0[mi]), "r"(a1[mi]), "r"(a2[mi]), "r"(a3[mi]),
                              "r"(b2), "r"(b3));
                    }
                }
            }
        }

        // Epilogue: direct fp32 stores (registers only).
#pragma unroll
        for (int mi = 0; mi < 2; mi++) {
#pragma unroll
            for (int h = 0; h < 2; h++) {
                int row = row0 + m0 + mi * 16 + (lane >> 2) + h * 8;
                if (row < N) {
                    float* Crow = C + (size_t)row * 128 + n0 + (lane & 3) * 2;
#pragma unroll
                    for (int nj = 0; nj < 4; nj++) {
                        *(float2*)(Crow + nj * 8) =
                            make_float2(c[mi][nj][h * 2], c[mi][nj][h * 2 + 1]);
                    }
                }
            }
        }
    }
}

// ---------------------------------------------------------------------------
// Pull aggregation: one warp per node, batched independent gathers.
// ---------------------------------------------------------------------------
__global__ void aggregate_kernel(const float* __restrict__ m,
                                 const int* __restrict__ counts,
                                 const int* __restrict__ slots,
                                 const float* __restrict__ bias,
                                 float* __restrict__ out, int N, int zeroCounts) {
    int warp = (blockIdx.x * blockDim.x + threadIdx.x) >> 5;
    int lane = threadIdx.x & 31;
    if (warp >= N) return;
    int cnt = counts[warp];
    if (cnt > MAXDEG) cnt = MAXDEG;
    const int* sl = slots + (size_t)warp * MAXDEG;

    // Coalesced prefetch of the first 32 indices.
    int myidx = (lane < cnt) ? __ldg(&sl[lane]) : 0;

    float4 acc = ((const float4*)bias)[lane];
    int idx = 0;
    const int cnt32 = cnt > 32 ? 32 : cnt;
    while (idx < cnt32) {
        int rem = cnt32 - idx;
        if (rem >= 8) {
            float4 v[8];
#pragma unroll
            for (int u = 0; u < 8; u++) {
                int s = __shfl_sync(0xFFFFFFFF, myidx, idx + u);
                v[u] = ((const float4*)(m + (size_t)s * 128))[lane];
            }
            float4 s01, s23, s45, s67, t0, t1;
            s01.x = v[0].x + v[1].x; s01.y = v[0].y + v[1].y; s01.z = v[0].z + v[1].z; s01.w = v[0].w + v[1].w;
            s23.x = v[2].x + v[3].x; s23.y = v[2].y + v[3].y; s23.z = v[2].z + v[3].z; s23.w = v[2].w + v[3].w;
            s45.x = v[4].x + v[5].x; s45.y = v[4].y + v[5].y; s45.z = v[4].z + v[5].z; s45.w = v[4].w + v[5].w;
            s67.x = v[6].x + v[7].x; s67.y = v[6].y + v[7].y; s67.z = v[6].z + v[7].z; s67.w = v[6].w + v[7].w;
            t0.x = s01.x + s23.x; t0.y = s01.y + s23.y; t0.z = s01.z + s23.z; t0.w = s01.w + s23.w;
            t1.x = s45.x + s67.x; t1.y = s45.y + s67.y; t1.z = s45.z + s67.z; t1.w = s45.w + s67.w;
            acc.x += t0.x + t1.x; acc.y += t0.y + t1.y; acc.z += t0.z + t1.z; acc.w += t0.w + t1.w;
            idx += 8;
        } else if (rem >= 4) {
            float4 v[4];
#pragma unroll
            for (int u = 0; u < 4; u++) {
                int s = __shfl_sync(0xFFFFFFFF, myidx, idx + u);
                v[u] = ((const float4*)(m + (size_t)s * 128))[lane];
            }
            float4 s01, s23;
            s01.x = v[0].x + v[1].x; s01.y = v[0].y + v[1].y; s01.z = v[0].z + v[1].z; s01.w = v[0].w + v[1].w;
            s23.x = v[2].x + v[3].x; s23.y = v[2].y + v[3].y; s23.z = v[2].z + v[3].z; s23.w = v[2].w + v[3].w;
            acc.x += s01.x + s23.x; acc.y += s01.y + s23.y; acc.z += s01.z + s23.z; acc.w += s01.w + s23.w;
            idx += 4;
        } else if (rem >= 2) {
            int s0 = __shfl_sync(0xFFFFFFFF, myidx, idx);
            int s1 = __shfl_sync(0xFFFFFFFF, myidx, idx + 1);
            float4 v0 = ((const float4*)(m + (size_t)s0 * 128))[lane];
            float4 v1 = ((const float4*)(m + (size_t)s1 * 128))[lane];
            acc.x += v0.x + v1.x; acc.y += v0.y + v1.y;
            acc.z += v0.z + v1.z; acc.w += v0.w + v1.w;
            idx += 2;
        } else {
            int s = __shfl_sync(0xFFFFFFFF, myidx, idx);
            float4 v = ((const float4*)(m + (size_t)s * 128))[lane];
            acc.x += v.x; acc.y += v.y; acc.z += v.z; acc.w += v.w;
            idx += 1;
        }
    }
    // Rare tail (deg > 32).
    for (; idx < cnt; idx++) {
        int s = __ldg(&sl[idx]);
        float4 v = ((const float4*)(m + (size_t)s * 128))[lane];
        acc.x += v.x; acc.y += v.y; acc.z += v.z; acc.w += v.w;
    }

    ((float4*)(out + (size_t)warp * 128))[lane] = acc;
    if (zeroCounts && lane == 0) ((int*)counts)[warp] = 0;
}

// ---------------------------------------------------------------------------
extern "C" void kernel_launch(void* const* d_in, const int* in_sizes, int n_in,
                              void* d_out, int out_size) {
    const float* x  = (const float*)d_in[0];
    const int*   ei = (const int*)d_in[1];
    const float* W1 = (const float*)d_in[2];
    const float* b1 = (const float*)d_in[3];
    const float* W2 = (const float*)d_in[4];
    const float* b2 = (const float*)d_in[5];
    float* out = (float*)d_out;

    const int N = in_sizes[0] / 128;
    const int E = in_sizes[1] / 2;
    const int* src = ei;
    const int* dst = ei + E;

    float* gm; float* gh;
    int *counts, *slots;
    unsigned short *wthi, *wtlo;
    cudaGetSymbolAddress((void**)&gm, g_m);
    cudaGetSymbolAddress((void**)&gh, g_h);
    cudaGetSymbolAddress((void**)&counts, g_counts);
    cudaGetSymbolAddress((void**)&slots, g_slots);
    cudaGetSymbolAddress((void**)&wthi, g_wthi);
    cudaGetSymbolAddress((void**)&wtlo, g_wtlo);

    cudaFuncSetAttribute(gemm_mma, cudaFuncAttributeMaxDynamicSharedMemorySize, GEMM_SMEM);

    const int numTiles = (N + 63) / 64;
    const int gemmGrid = numTiles < 296 ? numTiles : 296;   // 2 CTA/SM persistent
    const int prepGrid = 128 + (E + 255) / 256;
    const int aggGrid = (N + 7) / 8;

    // Fused prep: W conversion + slot-table build.
    prep_kernel<<<prepGrid, 256>>>(W1, W2, src, dst, counts, slots, E);

    // Layer 1.
    gemm_mma<<<gemmGrid, 256, GEMM_SMEM>>>(x, wthi, wtlo, gm, N, 0, numTiles);
    aggregate_kernel<<<aggGrid, 256>>>(gm, counts, slots, b1, gh, N, 0);

    // Layer 2 (ReLU fused into A conversion; final agg re-zeroes counts).
    gemm_mma<<<gemmGrid, 256, GEMM_SMEM>>>(gh, wthi + 128 * 128, wtlo + 128 * 128, gm, N, 1, numTiles);
    aggregate_kernel<<<aggGrid, 256>>>(gm, counts, slots, b2, out, N, 1);
}

// round 9
// speedup vs baseline: 1.4841x; 1.4841x over previous
#include <cuda_runtime.h>
#include <cuda_bf16.h>

#define NMAX 100000
#define MAXDEG 64

// ---------------- scratch (allocation-free) ----------------
__device__ float g_m[(size_t)NMAX * 128];
__device__ float g_h[(size_t)NMAX * 128];
__device__ int g_counts[NMAX];                    // zero-initialized at load
__device__ int g_slots[(size_t)NMAX * MAXDEG];    // incoming src per node
__device__ unsigned short g_wthi[2][128 * 128];
__device__ unsigned short g_wtlo[2][128 * 128];

__device__ __forceinline__ unsigned smem_u32(const void* p) {
    unsigned a;
    asm("{ .reg .u64 t; cvta.to.shared.u64 t, %1; cvt.u32.u64 %0, t; }" : "=r"(a) : "l"(p));
    return a;
}

// W tile layout: row-major 256B rows (n = 0..127, k bf16 cols); 16B chunks
// XOR-swizzled: chunk' = (k>>3) ^ (n & 7).
__device__ __forceinline__ unsigned tile_off(int row, int k) {
    return (unsigned)(row * 256 + ((((k >> 3) ^ (row & 7))) << 4) + (k & 7) * 2);
}

// ---------------------------------------------------------------------------
// Fused prep: blocks [0,128) convert W^T to bf16 hi/lo tiles;
// blocks [128, ...) place edges into the slot table.
// ---------------------------------------------------------------------------
__global__ void prep_kernel(const float* __restrict__ W1, const float* __restrict__ W2,
                            const int* __restrict__ src, const int* __restrict__ dst,
                            int* __restrict__ counts, int* __restrict__ slots, int E) {
    if (blockIdx.x < 128) {
        int id = blockIdx.x * 256 + threadIdx.x;   // 0..32767
        int layer = id >> 14;
        int nn = (id >> 7) & 127;
        int k = id & 127;
        const float* W = layer ? W2 : W1;
        float v = W[k * 128 + nn];                 // W^T[n][k]
        __nv_bfloat16 h = __float2bfloat16(v);
        __nv_bfloat16 l = __float2bfloat16(v - __bfloat162float(h));
        unsigned idx = tile_off(nn, k) >> 1;
        g_wthi[layer][idx] = *reinterpret_cast<unsigned short*>(&h);
        g_wtlo[layer][idx] = *reinterpret_cast<unsigned short*>(&l);
    } else {
        int e = (blockIdx.x - 128) * 256 + threadIdx.x;
        if (e < E) {
            int d = dst[e];
            int pos = atomicAdd(&counts[d], 1);
            if (pos < MAXDEG) slots[(size_t)d * MAXDEG + pos] = src[e];
        }
    }
}

// ---------------------------------------------------------------------------
// Warp-autonomous persistent GEMM: C[N,128] = (relu?)(A[N,128]) @ W
// Grid 296 x 256 thr (2 CTA/SM). W hi/lo resident in smem (64KB).
// Each WARP owns 16-row x 128-col tiles; A fragments loaded directly from
// global fp32 into registers (m16n8k16 layout), split into bf16 hi/lo.
// 3 products: Ah*Wh + Ah*Wl + Al*Wh, fp32 accum. No syncs in main loop.
// ---------------------------------------------------------------------------
#define WHI 0
#define WLO 32768
#define GEMM_SMEM 65536

#define MMA_OP(cc, A0, A1, A2, A3, B0, B1)                                       \
    asm volatile("mma.sync.aligned.m16n8k16.row.col.f32.bf16.bf16.f32 "          \
                 "{%0,%1,%2,%3}, {%4,%5,%6,%7}, {%8,%9}, {%0,%1,%2,%3};"         \
                 : "+f"((cc)[0]), "+f"((cc)[1]), "+f"((cc)[2]), "+f"((cc)[3])    \
                 : "r"(A0), "r"(A1), "r"(A2), "r"(A3), "r"(B0), "r"(B1))

__device__ __forceinline__ void split2(float2 v, unsigned& hi, unsigned& lo) {
    __nv_bfloat162 h = __floats2bfloat162_rn(v.x, v.y);
    float2 f = __bfloat1622float2(h);
    __nv_bfloat162 l = __floats2bfloat162_rn(v.x - f.x, v.y - f.y);
    hi = *reinterpret_cast<unsigned*>(&h);
    lo = *reinterpret_cast<unsigned*>(&l);
}

__global__ __launch_bounds__(256, 2) void gemm_mma(
    const float* __restrict__ A, const unsigned short* __restrict__ Whi,
    const unsigned short* __restrict__ Wlo, float* __restrict__ C,
    int N, int applyRelu, int numTiles) {
    extern __shared__ __align__(128) char smem[];
    const unsigned sb = smem_u32(smem);
    const int tx = threadIdx.x;
    const int lane = tx & 31;

    // Load W hi/lo once (2048 uint4 each).
    {
        const uint4* wh = (const uint4*)Whi;
        const uint4* wl = (const uint4*)Wlo;
        uint4* sh = (uint4*)(smem + WHI);
        uint4* sl = (uint4*)(smem + WLO);
#pragma unroll
        for (int i = 0; i < 8; i++) {
            sh[tx + 256 * i] = wh[tx + 256 * i];
            sl[tx + 256 * i] = wl[tx + 256 * i];
        }
    }
    __syncthreads();   // only sync: W resident for the whole kernel

    // ldmatrix lane addressing for W fragments (validated in R4/R6):
    // matrices: (n rows 0-7, k chunk 0), (rows 0-7, chunk 1), (rows 8-15, 0), (rows 8-15, 1)
    const int b_row_l = ((lane >> 4) << 3) + (lane & 7);
    const int b_half = (lane >> 3) & 1;
    const int sw_b = b_row_l & 7;

    // A fragment rows/cols for direct global load.
    const int ar = lane >> 2;        // row within m16 (and +8)
    const int ac = lane & 3;         // float2 col within k8 chunk

    const int warpGlobal = (blockIdx.x * 8) + (tx >> 5);
    const int totalWarps = gridDim.x * 8;
    const float2* A2 = (const float2*)A;

    for (int tile = warpGlobal; tile < numTiles; tile += totalWarps) {
        const int row0 = tile * 16;
        const int r0 = row0 + ar;
        const int r1 = r0 + 8;

        float c[8][8];
#pragma unroll
        for (int j = 0; j < 8; j++)
#pragma unroll
            for (int q = 0; q < 8; q++) c[j][q] = 0.f;

#pragma unroll
        for (int kk = 0; kk < 8; kk++) {
            const int kb = kk * 8;   // float2 offset of this k16 chunk
            // Direct global A fragment loads (fp32).
            float2 v00 = make_float2(0.f, 0.f), v01 = v00, v10 = v00, v11 = v00;
            if (r0 < N) {
                v00 = __ldg(&A2[(size_t)r0 * 64 + kb + ac]);
                v01 = __ldg(&A2[(size_t)r0 * 64 + kb + 4 + ac]);
            }
            if (r1 < N) {
                v10 = __ldg(&A2[(size_t)r1 * 64 + kb + ac]);
                v11 = __ldg(&A2[(size_t)r1 * 64 + kb + 4 + ac]);
            }
            if (applyRelu) {
                v00.x = fmaxf(v00.x, 0.f); v00.y = fmaxf(v00.y, 0.f);
                v01.x = fmaxf(v01.x, 0.f); v01.y = fmaxf(v01.y, 0.f);
                v10.x = fmaxf(v10.x, 0.f); v10.y = fmaxf(v10.y, 0.f);
                v11.x = fmaxf(v11.x, 0.f); v11.y = fmaxf(v11.y, 0.f);
            }
            // a0=(r0,k0-7) a1=(r1,k0-7) a2=(r0,k8-15) a3=(r1,k8-15)
            unsigned ah0, al0, ah1, al1, ah2, al2, ah3, al3;
            split2(v00, ah0, al0);
            split2(v10, ah1, al1);
            split2(v01, ah2, al2);
            split2(v11, ah3, al3);

            const unsigned kchunk = (unsigned)(((kk * 2 + b_half) ^ sw_b) << 4);
#pragma unroll
            for (int j = 0; j < 8; j++) {        // n16 groups
                const unsigned roff = (unsigned)((j * 16 + b_row_l) * 256) + kchunk;
                unsigned wh0, wh1, wh2, wh3, wl0, wl1, wl2, wl3;
                asm volatile("ldmatrix.sync.aligned.m8n8.x4.shared.b16 {%0,%1,%2,%3}, [%4];"
                             : "=r"(wh0), "=r"(wh1), "=r"(wh2), "=r"(wh3)
                             : "r"(sb + WHI + roff));
                asm volatile("ldmatrix.sync.aligned.m8n8.x4.shared.b16 {%0,%1,%2,%3}, [%4];"
                             : "=r"(wl0), "=r"(wl1), "=r"(wl2), "=r"(wl3)
                             : "r"(sb + WLO + roff));
                // n8 low (rows j*16+0..7): frag {wh0, wh1}; n8 high: {wh2, wh3}
                MMA_OP(c[j] + 0, ah0, ah1, ah2, ah3, wh0, wh1);
                MMA_OP(c[j] + 4, ah0, ah1, ah2, ah3, wh2, wh3);
                MMA_OP(c[j] + 0, al0, al1, al2, al3, wh0, wh1);
                MMA_OP(c[j] + 4, al0, al1, al2, al3, wh2, wh3);
                MMA_OP(c[j] + 0, ah0, ah1, ah2, ah3, wl0, wl1);
                MMA_OP(c[j] + 4, ah0, ah1, ah2, ah3, wl2, wl3);
            }
        }

        // Epilogue: c0,c1 -> (r0, col+0,1); c2,c3 -> (r1, col+0,1)
        if (r0 < N) {
            float* Crow = C + (size_t)r0 * 128 + (lane & 3) * 2;
#pragma unroll
            for (int j = 0; j < 8; j++) {
                *(float2*)(Crow + j * 16) = make_float2(c[j][0], c[j][1]);
                *(float2*)(Crow + j * 16 + 8) = make_float2(c[j][4], c[j][5]);
            }
        }
        if (r1 < N) {
            float* Crow = C + (size_t)r1 * 128 + (lane & 3) * 2;
#pragma unroll
            for (int j = 0; j < 8; j++) {
                *(float2*)(Crow + j * 16) = make_float2(c[j][2], c[j][3]);
                *(float2*)(Crow + j * 16 + 8) = make_float2(c[j][6], c[j][7]);
            }
        }
    }
}

// ---------------------------------------------------------------------------
// Pull aggregation (R6 version, measured 34us): one warp per node.
// ---------------------------------------------------------------------------
__global__ void aggregate_kernel(const float* __restrict__ m,
                                 const int* __restrict__ counts,
                                 const int* __restrict__ slots,
                                 const float* __restrict__ bias,
                                 float* __restrict__ out, int N, int zeroCounts) {
    int warp = (blockIdx.x * blockDim.x + threadIdx.x) >> 5;
    int lane = threadIdx.x & 31;
    if (warp >= N) return;
    int cnt = counts[warp];
    if (cnt > MAXDEG) cnt = MAXDEG;
    const int* sl = slots + (size_t)warp * MAXDEG;
    float4 acc = ((const float4*)bias)[lane];
    int idx = 0;
    for (; idx + 4 <= cnt; idx += 4) {
        int s0 = __ldg(&sl[idx]);
        int s1 = __ldg(&sl[idx + 1]);
        int s2 = __ldg(&sl[idx + 2]);
        int s3 = __ldg(&sl[idx + 3]);
        float4 v0 = ((const float4*)(m + (size_t)s0 * 128))[lane];
        float4 v1 = ((const float4*)(m + (size_t)s1 * 128))[lane];
        float4 v2 = ((const float4*)(m + (size_t)s2 * 128))[lane];
        float4 v3 = ((const float4*)(m + (size_t)s3 * 128))[lane];
        acc.x += v0.x + v1.x + v2.x + v3.x;
        acc.y += v0.y + v1.y + v2.y + v3.y;
        acc.z += v0.z + v1.z + v2.z + v3.z;
        acc.w += v0.w + v1.w + v2.w + v3.w;
    }
    for (; idx < cnt; idx++) {
        int s = __ldg(&sl[idx]);
        float4 v = ((const float4*)(m + (size_t)s * 128))[lane];
        acc.x += v.x; acc.y += v.y; acc.z += v.z; acc.w += v.w;
    }
    ((float4*)(out + (size_t)warp * 128))[lane] = acc;
    if (zeroCounts && lane == 0) ((int*)counts)[warp] = 0;
}

// ---------------------------------------------------------------------------
extern "C" void kernel_launch(void* const* d_in, const int* in_sizes, int n_in,
                              void* d_out, int out_size) {
    const float* x  = (const float*)d_in[0];
    const int*   ei = (const int*)d_in[1];
    const float* W1 = (const float*)d_in[2];
    const float* b1 = (const float*)d_in[3];
    const float* W2 = (const float*)d_in[4];
    const float* b2 = (const float*)d_in[5];
    float* out = (float*)d_out;

    const int N = in_sizes[0] / 128;
    const int E = in_sizes[1] / 2;
    const int* src = ei;
    const int* dst = ei + E;

    float* gm; float* gh;
    int *counts, *slots;
    unsigned short *wthi, *wtlo;
    cudaGetSymbolAddress((void**)&gm, g_m);
    cudaGetSymbolAddress((void**)&gh, g_h);
    cudaGetSymbolAddress((void**)&counts, g_counts);
    cudaGetSymbolAddress((void**)&slots, g_slots);
    cudaGetSymbolAddress((void**)&wthi, g_wthi);
    cudaGetSymbolAddress((void**)&wtlo, g_wtlo);

    cudaFuncSetAttribute(gemm_mma, cudaFuncAttributeMaxDynamicSharedMemorySize, GEMM_SMEM);

    const int numTiles = (N + 15) / 16;
    const int gemmGrid = 296;                       // 2 CTA/SM persistent
    const int prepGrid = 128 + (E + 255) / 256;
    const int aggGrid = (N + 7) / 8;

    // Fused prep: W conversion + slot-table build.
    prep_kernel<<<prepGrid, 256>>>(W1, W2, src, dst, counts, slots, E);

    // Layer 1.
    gemm_mma<<<gemmGrid, 256, GEMM_SMEM>>>(x, wthi, wtlo, gm, N, 0, numTiles);
    aggregate_kernel<<<aggGrid, 256>>>(gm, counts, slots, b1, gh, N, 0);

    // Layer 2 (ReLU fused into A fragment load; final agg re-zeroes counts).
    gemm_mma<<<gemmGrid, 256, GEMM_SMEM>>>(gh, wthi + 128 * 128, wtlo + 128 * 128, gm, N, 1, numTiles);
    aggregate_kernel<<<aggGrid, 256>>>(gm, counts, slots, b2, out, N, 1);
}